// round 1
// baseline (speedup 1.0000x reference)
#include <cuda_runtime.h>
#include <cuda_bf16.h>
#include <math.h>

// Problem constants
#define BATCH 2
#define TT 2048
#define DD 2048
#define HK 16
#define HV 32
#define KD 128
#define VD 128
#define KEY_DIM 2048
#define VALUE_DIM 4096
#define QKVZ_N 12288   // 2*KEY_DIM + 2*VALUE_DIM
#define BT (BATCH*TT)  // 4096

// ---------------------------------------------------------------------------
// Scratch (static device globals; no allocation at runtime)
// ---------------------------------------------------------------------------
__device__ float g_qkvz[(size_t)BT * QKVZ_N];      // 201 MB
__device__ float g_ba  [(size_t)BT * 64];
__device__ float g_qn  [(size_t)BT * HV * KD];     // 67 MB  [b,t,h,k]
__device__ float g_kn  [(size_t)BT * HV * KD];     // 67 MB
__device__ float g_v   [(size_t)BT * HV * VD];     // 67 MB
__device__ float g_o   [(size_t)BT * HV * VD];     // 67 MB
__device__ float g_x   [(size_t)BT * VALUE_DIM];   // 67 MB
__device__ float g_g   [(size_t)BT * HV];
__device__ float g_beta[(size_t)BT * HV];

// ---------------------------------------------------------------------------
// fp32 SGEMM: C[M,N] = A[M,K] * B[K,N], row-major. M%128==0, N%128==0, K%8==0
// ---------------------------------------------------------------------------
#define GBM 128
#define GBN 128
#define GBK 8
#define GTM 8
#define GTN 8

__global__ __launch_bounds__(256) void sgemm_kernel(
    const float* __restrict__ A, const float* __restrict__ B,
    float* __restrict__ C, int M, int N, int Kd)
{
    __shared__ float As[GBK][GBM];
    __shared__ float Bs[GBK][GBN];
    const int bx = blockIdx.x;            // N tile
    const int by = blockIdx.y;            // M tile
    const int tid = threadIdx.x;
    const int tx = tid & 15;
    const int ty = tid >> 4;
    // A tile load: 128 rows x 8 cols; each thread 1 float4
    const int aRow = tid >> 1;
    const int aCol = (tid & 1) * 4;
    // B tile load: 8 rows x 128 cols; each thread 1 float4
    const int bRow = tid >> 5;
    const int bCol = (tid & 31) * 4;

    const float* Ab = A + (size_t)(by * GBM) * Kd;
    const float* Bb = B + (size_t)(bx * GBN);

    float acc[GTM][GTN];
#pragma unroll
    for (int i = 0; i < GTM; i++)
#pragma unroll
        for (int j = 0; j < GTN; j++) acc[i][j] = 0.f;

    for (int k0 = 0; k0 < Kd; k0 += GBK) {
        float4 av = *(const float4*)(Ab + (size_t)aRow * Kd + k0 + aCol);
        As[aCol + 0][aRow] = av.x;
        As[aCol + 1][aRow] = av.y;
        As[aCol + 2][aRow] = av.z;
        As[aCol + 3][aRow] = av.w;
        float4 bv = *(const float4*)(Bb + (size_t)(k0 + bRow) * N + bCol);
        *(float4*)&Bs[bRow][bCol] = bv;
        __syncthreads();
#pragma unroll
        for (int kk = 0; kk < GBK; kk++) {
            float rm[GTM], rn[GTN];
            float4 m0 = *(const float4*)&As[kk][ty * GTM];
            float4 m1 = *(const float4*)&As[kk][ty * GTM + 4];
            rm[0]=m0.x; rm[1]=m0.y; rm[2]=m0.z; rm[3]=m0.w;
            rm[4]=m1.x; rm[5]=m1.y; rm[6]=m1.z; rm[7]=m1.w;
            float4 n0 = *(const float4*)&Bs[kk][tx * GTN];
            float4 n1 = *(const float4*)&Bs[kk][tx * GTN + 4];
            rn[0]=n0.x; rn[1]=n0.y; rn[2]=n0.z; rn[3]=n0.w;
            rn[4]=n1.x; rn[5]=n1.y; rn[6]=n1.z; rn[7]=n1.w;
#pragma unroll
            for (int i = 0; i < GTM; i++)
#pragma unroll
                for (int j = 0; j < GTN; j++)
                    acc[i][j] += rm[i] * rn[j];
        }
        __syncthreads();
    }

    float* Cb = C + (size_t)(by * GBM + ty * GTM) * N + bx * GBN + tx * GTN;
#pragma unroll
    for (int i = 0; i < GTM; i++) {
#pragma unroll
        for (int j = 0; j < GTN; j += 4) {
            float4 w;
            w.x = acc[i][j + 0]; w.y = acc[i][j + 1];
            w.z = acc[i][j + 2]; w.w = acc[i][j + 3];
            *(float4*)(Cb + (size_t)i * N + j) = w;
        }
    }
}

// ---------------------------------------------------------------------------
// ba = hs @ W_ba   (4096 x 64, K=2048). One block per row.
// ---------------------------------------------------------------------------
__global__ __launch_bounds__(64) void ba_kernel(
    const float* __restrict__ hs, const float* __restrict__ Wba,
    float* __restrict__ ba)
{
    __shared__ float hrow[DD];
    const int row = blockIdx.x;
    for (int i = threadIdx.x; i < DD; i += 64)
        hrow[i] = hs[(size_t)row * DD + i];
    __syncthreads();
    float acc = 0.f;
    const float* wb = Wba + threadIdx.x;
    for (int k = 0; k < DD; k++)
        acc += hrow[k] * wb[(size_t)k * 64];
    ba[(size_t)row * 64 + threadIdx.x] = acc;
}

// ---------------------------------------------------------------------------
// Fused: causal conv4 + SiLU over q,k,v channels; per-key-head l2norm;
// GQA expand (x2) with q scale; v store; gating (beta, g).
// One block per (b,t).
// ---------------------------------------------------------------------------
__device__ __forceinline__ float silu_f(float x) {
    return x / (1.f + __expf(-x));
}

__global__ __launch_bounds__(256) void conv_gate_kernel(
    const float* __restrict__ qkvz, const float* __restrict__ ba,
    const float* __restrict__ convw, const float* __restrict__ Alog,
    const float* __restrict__ dtb,
    float* __restrict__ qn, float* __restrict__ kn, float* __restrict__ vv,
    float* __restrict__ gg, float* __restrict__ bb)
{
    const int bt = blockIdx.x;
    const int b = bt / TT;
    const int t = bt % TT;
    const int tid = threadIdx.x;
    __shared__ float buf[2 * KEY_DIM];   // conv(q)=0..2047, conv(k)=2048..4095
    __shared__ float rnorm[2 * HK];      // q-head rsqrt (0..15), k-head (16..31)

    // conv + silu for q,k channels (0..4095)
    for (int c = tid; c < 2 * KEY_DIM; c += 256) {
        float acc = 0.f;
#pragma unroll
        for (int j = 0; j < 4; j++) {
            int ts = t - 3 + j;
            if (ts >= 0)
                acc += convw[c * 4 + j] *
                       qkvz[((size_t)b * TT + ts) * QKVZ_N + c];
        }
        buf[c] = silu_f(acc);
    }
    __syncthreads();

    // per-head sum of squares (32 groups of 128), one warp per 4 groups
    const int warp = tid >> 5;
    const int lane = tid & 31;
    for (int gi = warp; gi < 32; gi += 8) {
        float s = 0.f;
#pragma unroll
        for (int l = 0; l < 4; l++) {
            float x = buf[gi * 128 + lane + 32 * l];
            s += x * x;
        }
#pragma unroll
        for (int off = 16; off; off >>= 1)
            s += __shfl_xor_sync(0xffffffffu, s, off);
        if (lane == 0) rnorm[gi] = rsqrtf(s + 1e-6f);
    }
    __syncthreads();

    // write normalized + GQA-expanded q,k  ([b,t,HV,KD])
    const float QSCALE = 0.08838834764831845f;  // 128^-0.5
    for (int i = tid; i < KEY_DIM; i += 256) {
        int kh = i >> 7;
        int d  = i & 127;
        float qv = buf[i] * rnorm[kh] * QSCALE;
        float kv = buf[KEY_DIM + i] * rnorm[HK + kh];
        size_t o0 = ((size_t)bt * HV + 2 * kh) * KD + d;
        qn[o0] = qv;  qn[o0 + KD] = qv;
        kn[o0] = kv;  kn[o0 + KD] = kv;
    }

    // conv + silu for v channels (4096..8191) -> direct store
    for (int c = tid; c < VALUE_DIM; c += 256) {
        int cc = 2 * KEY_DIM + c;
        float acc = 0.f;
#pragma unroll
        for (int j = 0; j < 4; j++) {
            int ts = t - 3 + j;
            if (ts >= 0)
                acc += convw[cc * 4 + j] *
                       qkvz[((size_t)b * TT + ts) * QKVZ_N + cc];
        }
        vv[(size_t)bt * VALUE_DIM + c] = silu_f(acc);
    }

    // gating
    if (tid < HV) {
        float bg = ba[(size_t)bt * 64 + tid];
        float a  = ba[(size_t)bt * 64 + 32 + tid] + dtb[tid];
        bb[(size_t)bt * HV + tid] = 1.f / (1.f + __expf(-bg));
        float sp = (a > 20.f) ? a : log1pf(__expf(a));
        gg[(size_t)bt * HV + tid] = -__expf(Alog[tid]) * sp;
    }
}

// ---------------------------------------------------------------------------
// Gated delta-rule scan. One block per (b,h): 64 blocks, 128 threads.
// Thread v owns state column S[0..127][v] in registers.
// ---------------------------------------------------------------------------
__global__ __launch_bounds__(128, 1) void scan_kernel(
    const float* __restrict__ qn, const float* __restrict__ kn,
    const float* __restrict__ vv, const float* __restrict__ gg,
    const float* __restrict__ bb, float* __restrict__ oo)
{
    const int b = blockIdx.x >> 5;   // 0..1
    const int h = blockIdx.x & 31;   // 0..31
    const int v = threadIdx.x;       // 0..127

    float S[KD];
#pragma unroll
    for (int i = 0; i < KD; i++) S[i] = 0.f;

    __shared__ float sk[KD], sq[KD];
    __shared__ float s_eg, s_beta;

    for (int t = 0; t < TT; t++) {
        const size_t idx = (((size_t)b * TT + t) * HV + h) * (size_t)KD;
        sk[v] = kn[idx + v];
        sq[v] = qn[idx + v];
        float vt = vv[idx + v];
        if (v == 0) {
            size_t gi = ((size_t)b * TT + t) * HV + h;
            s_eg = __expf(gg[gi]);
            s_beta = bb[gi];
        }
        __syncthreads();
        const float eg = s_eg;
        const float beta = s_beta;

        // decay + pred = k . S   (4 accumulators to break FFMA chain)
        float p0 = 0.f, p1 = 0.f, p2 = 0.f, p3 = 0.f;
#pragma unroll
        for (int k = 0; k < KD; k += 4) {
            float4 kv = *(const float4*)&sk[k];
            S[k + 0] *= eg; p0 += kv.x * S[k + 0];
            S[k + 1] *= eg; p1 += kv.y * S[k + 1];
            S[k + 2] *= eg; p2 += kv.z * S[k + 2];
            S[k + 3] *= eg; p3 += kv.w * S[k + 3];
        }
        const float delta = (vt - (p0 + p1 + p2 + p3)) * beta;

        // update + out = q . S
        float o0 = 0.f, o1 = 0.f, o2 = 0.f, o3 = 0.f;
#pragma unroll
        for (int k = 0; k < KD; k += 4) {
            float4 kv = *(const float4*)&sk[k];
            float4 qv = *(const float4*)&sq[k];
            S[k + 0] += kv.x * delta; o0 += qv.x * S[k + 0];
            S[k + 1] += kv.y * delta; o1 += qv.y * S[k + 1];
            S[k + 2] += kv.z * delta; o2 += qv.z * S[k + 2];
            S[k + 3] += kv.w * delta; o3 += qv.w * S[k + 3];
        }
        oo[idx + v] = o0 + o1 + o2 + o3;
        __syncthreads();
    }
}

// ---------------------------------------------------------------------------
// x = o * silu(z); per-head RMSNorm; apply (1+norm_weight). One block per (b,t).
// ---------------------------------------------------------------------------
__global__ __launch_bounds__(256) void rmsnorm_kernel(
    const float* __restrict__ oo, const float* __restrict__ qkvz,
    const float* __restrict__ nw, float* __restrict__ xout)
{
    const int bt = blockIdx.x;
    const int warp = threadIdx.x >> 5;
    const int lane = threadIdx.x & 31;

    for (int hh = warp; hh < HV; hh += 8) {
        const size_t base = ((size_t)bt * HV + hh) * (size_t)VD;
        const float* zz = qkvz + (size_t)bt * QKVZ_N + 2 * KEY_DIM + VALUE_DIM
                          + (size_t)hh * VD;
        float xv[4];
        float ss = 0.f;
#pragma unroll
        for (int i = 0; i < 4; i++) {
            int d = lane + 32 * i;
            float z = zz[d];
            float x = oo[base + d] * silu_f(z);
            xv[i] = x;
            ss += x * x;
        }
#pragma unroll
        for (int off = 16; off; off >>= 1)
            ss += __shfl_xor_sync(0xffffffffu, ss, off);
        float r = rsqrtf(ss * (1.f / 128.f) + 1e-6f);
#pragma unroll
        for (int i = 0; i < 4; i++) {
            int d = lane + 32 * i;
            xout[(size_t)bt * VALUE_DIM + hh * VD + d] =
                xv[i] * r * (1.f + nw[d]);
        }
    }
}

// ---------------------------------------------------------------------------
// Launch
// ---------------------------------------------------------------------------
extern "C" void kernel_launch(void* const* d_in, const int* in_sizes, int n_in,
                              void* d_out, int out_size)
{
    const float* hs    = (const float*)d_in[0];
    const float* Wqkvz = (const float*)d_in[1];
    const float* Wba   = (const float*)d_in[2];
    const float* convw = (const float*)d_in[3];
    const float* Alog  = (const float*)d_in[4];
    const float* dtb   = (const float*)d_in[5];
    const float* nw    = (const float*)d_in[6];
    const float* Wout  = (const float*)d_in[7];
    float* out = (float*)d_out;

    float *qkvz, *ba, *qn, *kn, *vv, *oo, *xx, *gg, *bb;
    cudaGetSymbolAddress((void**)&qkvz, g_qkvz);
    cudaGetSymbolAddress((void**)&ba,   g_ba);
    cudaGetSymbolAddress((void**)&qn,   g_qn);
    cudaGetSymbolAddress((void**)&kn,   g_kn);
    cudaGetSymbolAddress((void**)&vv,   g_v);
    cudaGetSymbolAddress((void**)&oo,   g_o);
    cudaGetSymbolAddress((void**)&xx,   g_x);
    cudaGetSymbolAddress((void**)&gg,   g_g);
    cudaGetSymbolAddress((void**)&bb,   g_beta);

    // 1) qkvz = hs @ W_qkvz : [4096,2048]x[2048,12288]
    sgemm_kernel<<<dim3(QKVZ_N / GBN, BT / GBM), 256>>>(
        hs, Wqkvz, qkvz, BT, QKVZ_N, DD);

    // 2) ba = hs @ W_ba : [4096,2048]x[2048,64]
    ba_kernel<<<BT, 64>>>(hs, Wba, ba);

    // 3) conv + silu + l2norm + GQA expand + gating
    conv_gate_kernel<<<BT, 256>>>(qkvz, ba, convw, Alog, dtb,
                                  qn, kn, vv, gg, bb);

    // 4) gated delta rule scan
    scan_kernel<<<BATCH * HV, 128>>>(qn, kn, vv, gg, bb, oo);

    // 5) gated rmsnorm
    rmsnorm_kernel<<<BT, 256>>>(oo, qkvz, nw, xx);

    // 6) out = x @ W_out : [4096,4096]x[4096,2048]
    sgemm_kernel<<<dim3(DD / GBN, BT / GBM), 256>>>(
        xx, Wout, out, BT, DD, VALUE_DIM);
}

// round 2
// speedup vs baseline: 2.0002x; 2.0002x over previous
#include <cuda_runtime.h>
#include <cuda_bf16.h>
#include <math.h>

typedef unsigned long long ull;
typedef unsigned int u32;

// Problem constants
#define BATCH 2
#define TT 2048
#define DD 2048
#define HK 16
#define HV 32
#define KD 128
#define VD 128
#define KEY_DIM 2048
#define VALUE_DIM 4096
#define QKVZ_N 12288   // 2*KEY_DIM + 2*VALUE_DIM
#define BT (BATCH*TT)  // 4096

// ---------------------------------------------------------------------------
// Scratch (static device globals; no allocation at runtime)
// ---------------------------------------------------------------------------
__device__ float g_qkvz[(size_t)BT * QKVZ_N];      // 201 MB
__device__ float g_ba  [(size_t)BT * 64];
__device__ float g_qn  [(size_t)BT * HK * KD];     // 33.5 MB [b,t,kh,k] (not expanded)
__device__ float g_kn  [(size_t)BT * HK * KD];     // 33.5 MB
__device__ float g_v   [(size_t)BT * HV * VD];     // 67 MB
__device__ float g_o   [(size_t)BT * HV * VD];     // 67 MB
__device__ float g_x   [(size_t)BT * VALUE_DIM];   // 67 MB
__device__ float g_g   [(size_t)BT * HV];
__device__ float g_beta[(size_t)BT * HV];

// ---------------------------------------------------------------------------
// f32x2 packed math helpers (Blackwell; ptxas never auto-fuses these)
// ---------------------------------------------------------------------------
__device__ __forceinline__ ull ffma2(ull a, ull b, ull c) {
    ull d; asm("fma.rn.f32x2 %0, %1, %2, %3;" : "=l"(d) : "l"(a), "l"(b), "l"(c));
    return d;
}
__device__ __forceinline__ ull fmul2(ull a, ull b) {
    ull d; asm("mul.rn.f32x2 %0, %1, %2;" : "=l"(d) : "l"(a), "l"(b));
    return d;
}
__device__ __forceinline__ ull pack2(float x, float y) {
    ull r; asm("mov.b64 %0, {%1, %2};" : "=l"(r) : "f"(x), "f"(y));
    return r;
}
__device__ __forceinline__ float lo2(ull a) { return __uint_as_float((u32)(a & 0xffffffffull)); }
__device__ __forceinline__ float hi2(ull a) { return __uint_as_float((u32)(a >> 32)); }

__device__ __forceinline__ u32 f2tf(float x) {
    u32 r; asm("cvt.rna.tf32.f32 %0, %1;" : "=r"(r) : "f"(x));
    return r;
}
__device__ __forceinline__ float silu_f(float x) {
    return x / (1.f + __expf(-x));
}

// ---------------------------------------------------------------------------
// tf32 tensor-core GEMM: C[M,N] = A[M,K] * B[K,N], row-major.
// Block 128x128x32, 256 threads (8 warps), warp tile 32x64 (m16n8k8 mma).
// M%128==0, N%128==0, K%32==0.
// ---------------------------------------------------------------------------
#define BM 128
#define BN 128
#define BK 32
#define AS_STR (BK + 4)    // 36: bank = 4*row + col -> conflict-free A frags
#define BS_STR (BN + 8)    // 136: bank = 8*k + n    -> conflict-free B frags

__global__ __launch_bounds__(256) void tf32_gemm_kernel(
    const float* __restrict__ A, const float* __restrict__ B,
    float* __restrict__ C, int M, int N, int Kd)
{
    __shared__ __align__(16) u32 As[BM][AS_STR];
    __shared__ __align__(16) u32 Bs[BK][BS_STR];

    const int tid = threadIdx.x;
    const int bx = blockIdx.x;     // N tile
    const int by = blockIdx.y;     // M tile
    const int warp = tid >> 5;
    const int lane = tid & 31;
    const int group = lane >> 2;   // 0..7
    const int tg = lane & 3;       // 0..3
    const int warp_m = warp >> 1;  // 0..3
    const int warp_n = warp & 1;   // 0..1

    // global load mapping
    const int arow = tid >> 3;             // 0..31 (+i*32)
    const int acol = (tid & 7) * 4;        // 0..28
    const int brow = tid >> 5;             // 0..7  (+i*8)
    const int bcol = (tid & 31) * 4;       // 0..124

    const float* Ag = A + (size_t)(by * BM) * Kd;
    const float* Bg = B + (size_t)(bx * BN);

    float acc[2][8][4];
#pragma unroll
    for (int mt = 0; mt < 2; mt++)
#pragma unroll
        for (int nt = 0; nt < 8; nt++)
#pragma unroll
            for (int r = 0; r < 4; r++) acc[mt][nt][r] = 0.f;

    for (int k0 = 0; k0 < Kd; k0 += BK) {
        // load A tile 128x32
#pragma unroll
        for (int i = 0; i < 4; i++) {
            int r = arow + i * 32;
            float4 v = *(const float4*)(Ag + (size_t)r * Kd + k0 + acol);
            u32 t4[4] = { f2tf(v.x), f2tf(v.y), f2tf(v.z), f2tf(v.w) };
            *(uint4*)&As[r][acol] = *(uint4*)t4;
        }
        // load B tile 32x128
#pragma unroll
        for (int i = 0; i < 4; i++) {
            int kr = brow + i * 8;
            float4 v = *(const float4*)(Bg + (size_t)(k0 + kr) * N + bcol);
            u32 t4[4] = { f2tf(v.x), f2tf(v.y), f2tf(v.z), f2tf(v.w) };
            *(uint4*)&Bs[kr][bcol] = *(uint4*)t4;
        }
        __syncthreads();

#pragma unroll
        for (int ks = 0; ks < BK; ks += 8) {
            u32 af[2][4];
#pragma unroll
            for (int mt = 0; mt < 2; mt++) {
                int r0 = warp_m * 32 + mt * 16 + group;
                af[mt][0] = As[r0    ][ks + tg];
                af[mt][1] = As[r0 + 8][ks + tg];
                af[mt][2] = As[r0    ][ks + tg + 4];
                af[mt][3] = As[r0 + 8][ks + tg + 4];
            }
            u32 bf[8][2];
#pragma unroll
            for (int nt = 0; nt < 8; nt++) {
                int c0 = warp_n * 64 + nt * 8 + group;
                bf[nt][0] = Bs[ks + tg    ][c0];
                bf[nt][1] = Bs[ks + tg + 4][c0];
            }
#pragma unroll
            for (int mt = 0; mt < 2; mt++)
#pragma unroll
                for (int nt = 0; nt < 8; nt++) {
                    asm volatile(
                        "mma.sync.aligned.m16n8k8.row.col.f32.tf32.tf32.f32 "
                        "{%0,%1,%2,%3}, {%4,%5,%6,%7}, {%8,%9}, {%0,%1,%2,%3};\n"
                        : "+f"(acc[mt][nt][0]), "+f"(acc[mt][nt][1]),
                          "+f"(acc[mt][nt][2]), "+f"(acc[mt][nt][3])
                        : "r"(af[mt][0]), "r"(af[mt][1]), "r"(af[mt][2]), "r"(af[mt][3]),
                          "r"(bf[nt][0]), "r"(bf[nt][1]));
                }
        }
        __syncthreads();
    }

    // epilogue
#pragma unroll
    for (int mt = 0; mt < 2; mt++) {
        int row = by * BM + warp_m * 32 + mt * 16 + group;
#pragma unroll
        for (int nt = 0; nt < 8; nt++) {
            int col = bx * BN + warp_n * 64 + nt * 8 + tg * 2;
            float2 w0 = make_float2(acc[mt][nt][0], acc[mt][nt][1]);
            float2 w1 = make_float2(acc[mt][nt][2], acc[mt][nt][3]);
            *(float2*)(C + (size_t)row * N + col) = w0;
            *(float2*)(C + (size_t)(row + 8) * N + col) = w1;
        }
    }
}

// ---------------------------------------------------------------------------
// ba = hs @ W_ba   (4096 x 64, K=2048). One block per row.
// ---------------------------------------------------------------------------
__global__ __launch_bounds__(64) void ba_kernel(
    const float* __restrict__ hs, const float* __restrict__ Wba,
    float* __restrict__ ba)
{
    __shared__ float hrow[DD];
    const int row = blockIdx.x;
    for (int i = threadIdx.x; i < DD; i += 64)
        hrow[i] = hs[(size_t)row * DD + i];
    __syncthreads();
    float acc = 0.f;
    const float* wb = Wba + threadIdx.x;
    for (int k = 0; k < DD; k++)
        acc += hrow[k] * wb[(size_t)k * 64];
    ba[(size_t)row * 64 + threadIdx.x] = acc;
}

// ---------------------------------------------------------------------------
// Fused: causal conv4 + SiLU over q,k,v channels; per-key-head l2norm;
// q-scale; v store; gating (beta, g). q/k stored NON-expanded [bt,HK,KD].
// One block per (b,t).
// ---------------------------------------------------------------------------
__global__ __launch_bounds__(256) void conv_gate_kernel(
    const float* __restrict__ qkvz, const float* __restrict__ ba,
    const float* __restrict__ convw, const float* __restrict__ Alog,
    const float* __restrict__ dtb,
    float* __restrict__ qn, float* __restrict__ kn, float* __restrict__ vv,
    float* __restrict__ gg, float* __restrict__ bb)
{
    const int bt = blockIdx.x;
    const int b = bt / TT;
    const int t = bt % TT;
    const int tid = threadIdx.x;
    __shared__ float buf[2 * KEY_DIM];
    __shared__ float rnorm[2 * HK];

    for (int c = tid; c < 2 * KEY_DIM; c += 256) {
        float acc = 0.f;
#pragma unroll
        for (int j = 0; j < 4; j++) {
            int ts = t - 3 + j;
            if (ts >= 0)
                acc += convw[c * 4 + j] *
                       qkvz[((size_t)b * TT + ts) * QKVZ_N + c];
        }
        buf[c] = silu_f(acc);
    }
    __syncthreads();

    const int warp = tid >> 5;
    const int lane = tid & 31;
    for (int gi = warp; gi < 32; gi += 8) {
        float s = 0.f;
#pragma unroll
        for (int l = 0; l < 4; l++) {
            float x = buf[gi * 128 + lane + 32 * l];
            s += x * x;
        }
#pragma unroll
        for (int off = 16; off; off >>= 1)
            s += __shfl_xor_sync(0xffffffffu, s, off);
        if (lane == 0) rnorm[gi] = rsqrtf(s + 1e-6f);
    }
    __syncthreads();

    const float QSCALE = 0.08838834764831845f;  // 128^-0.5
    for (int i = tid; i < KEY_DIM; i += 256) {
        int kh = i >> 7;
        int d  = i & 127;
        size_t o0 = ((size_t)bt * HK + kh) * KD + d;
        qn[o0] = buf[i] * rnorm[kh] * QSCALE;
        kn[o0] = buf[KEY_DIM + i] * rnorm[HK + kh];
    }

    for (int c = tid; c < VALUE_DIM; c += 256) {
        int cc = 2 * KEY_DIM + c;
        float acc = 0.f;
#pragma unroll
        for (int j = 0; j < 4; j++) {
            int ts = t - 3 + j;
            if (ts >= 0)
                acc += convw[cc * 4 + j] *
                       qkvz[((size_t)b * TT + ts) * QKVZ_N + cc];
        }
        vv[(size_t)bt * VALUE_DIM + c] = silu_f(acc);
    }

    if (tid < HV) {
        float bg = ba[(size_t)bt * 64 + tid];
        float a  = ba[(size_t)bt * 64 + 32 + tid] + dtb[tid];
        bb[(size_t)bt * HV + tid] = 1.f / (1.f + __expf(-bg));
        float sp = (a > 20.f) ? a : log1pf(__expf(a));
        gg[(size_t)bt * HV + tid] = -__expf(Alog[tid]) * sp;
    }
}

// ---------------------------------------------------------------------------
// Gated delta-rule scan.
// 128 blocks = (b, h, vhalf). 256 threads: 64 v-columns x 4 k-quarters.
// Thread owns S[k-quarter, vcol] = 32 floats (16 packed f32x2).
// No barriers: pred/out reductions are 4-lane shuffles. Register
// double-buffered prefetch of next step's q/k/v/g/beta.
// ---------------------------------------------------------------------------
struct ScanBuf {
    ulonglong2 k[8];   // 32 floats
    ulonglong2 q[8];
    float v, g, beta;
};

__device__ __forceinline__ void scan_load(
    ScanBuf& sb, int t, int b, int kh, int h, int kq, int vcol,
    const float* __restrict__ qn, const float* __restrict__ kn,
    const float* __restrict__ vv, const float* __restrict__ gg,
    const float* __restrict__ bb)
{
    int tc = t < TT ? t : TT - 1;
    size_t ik = (((size_t)b * TT + tc) * HK + kh) * (size_t)KD + kq * 32;
    size_t iv = (((size_t)b * TT + tc) * HV + h) * (size_t)VD + vcol;
    const ulonglong2* kp = (const ulonglong2*)(kn + ik);
    const ulonglong2* qp = (const ulonglong2*)(qn + ik);
#pragma unroll
    for (int i = 0; i < 8; i++) { sb.k[i] = kp[i]; sb.q[i] = qp[i]; }
    sb.v = vv[iv];
    size_t ig = ((size_t)b * TT + tc) * HV + h;
    sb.g = gg[ig];
    sb.beta = bb[ig];
}

__device__ __forceinline__ void scan_step(
    ull* __restrict__ S2, const ScanBuf& sb, int t, int b, int h, int kq,
    int vcol, float* __restrict__ oo)
{
    float eg = __expf(sb.g);
    ull eg2 = pack2(eg, eg);
    ull p2 = 0ull;
#pragma unroll
    for (int i = 0; i < 8; i++) {
        S2[2*i]   = fmul2(S2[2*i],   eg2);
        p2 = ffma2(sb.k[i].x, S2[2*i],   p2);
        S2[2*i+1] = fmul2(S2[2*i+1], eg2);
        p2 = ffma2(sb.k[i].y, S2[2*i+1], p2);
    }
    float p = lo2(p2) + hi2(p2);
    p += __shfl_xor_sync(0xffffffffu, p, 1);
    p += __shfl_xor_sync(0xffffffffu, p, 2);
    float delta = (sb.v - p) * sb.beta;
    ull d2 = pack2(delta, delta);
    ull o2 = 0ull;
#pragma unroll
    for (int i = 0; i < 8; i++) {
        S2[2*i]   = ffma2(sb.k[i].x, d2, S2[2*i]);
        o2 = ffma2(sb.q[i].x, S2[2*i],   o2);
        S2[2*i+1] = ffma2(sb.k[i].y, d2, S2[2*i+1]);
        o2 = ffma2(sb.q[i].y, S2[2*i+1], o2);
    }
    float o = lo2(o2) + hi2(o2);
    o += __shfl_xor_sync(0xffffffffu, o, 1);
    o += __shfl_xor_sync(0xffffffffu, o, 2);
    if (kq == 0) {
        size_t iv = (((size_t)b * TT + t) * HV + h) * (size_t)VD + vcol;
        oo[iv] = o;
    }
}

__global__ __launch_bounds__(256, 1) void scan_kernel(
    const float* __restrict__ qn, const float* __restrict__ kn,
    const float* __restrict__ vv, const float* __restrict__ gg,
    const float* __restrict__ bb, float* __restrict__ oo)
{
    const int bh2 = blockIdx.x;        // 0..127
    const int b = bh2 >> 6;
    const int rem = bh2 & 63;
    const int h = rem >> 1;            // 0..31
    const int vhalf = rem & 1;
    const int tid = threadIdx.x;
    const int colL = tid >> 2;         // 0..63
    const int kq = tid & 3;            // 0..3
    const int vcol = vhalf * 64 + colL;
    const int kh = h >> 1;

    ull S2[16];
#pragma unroll
    for (int i = 0; i < 16; i++) S2[i] = 0ull;

    ScanBuf bA, bB;
    scan_load(bA, 0, b, kh, h, kq, vcol, qn, kn, vv, gg, bb);

    for (int t = 0; t < TT; t += 2) {
        scan_load(bB, t + 1, b, kh, h, kq, vcol, qn, kn, vv, gg, bb);
        scan_step(S2, bA, t, b, h, kq, vcol, oo);
        scan_load(bA, t + 2, b, kh, h, kq, vcol, qn, kn, vv, gg, bb);
        scan_step(S2, bB, t + 1, b, h, kq, vcol, oo);
    }
}

// ---------------------------------------------------------------------------
// x = o * silu(z); per-head RMSNorm; apply (1+norm_weight). One block per (b,t).
// ---------------------------------------------------------------------------
__global__ __launch_bounds__(256) void rmsnorm_kernel(
    const float* __restrict__ oo, const float* __restrict__ qkvz,
    const float* __restrict__ nw, float* __restrict__ xout)
{
    const int bt = blockIdx.x;
    const int warp = threadIdx.x >> 5;
    const int lane = threadIdx.x & 31;

    for (int hh = warp; hh < HV; hh += 8) {
        const size_t base = ((size_t)bt * HV + hh) * (size_t)VD;
        const float* zz = qkvz + (size_t)bt * QKVZ_N + 2 * KEY_DIM + VALUE_DIM
                          + (size_t)hh * VD;
        float xv[4];
        float ss = 0.f;
#pragma unroll
        for (int i = 0; i < 4; i++) {
            int d = lane + 32 * i;
            float z = zz[d];
            float x = oo[base + d] * silu_f(z);
            xv[i] = x;
            ss += x * x;
        }
#pragma unroll
        for (int off = 16; off; off >>= 1)
            ss += __shfl_xor_sync(0xffffffffu, ss, off);
        float r = rsqrtf(ss * (1.f / 128.f) + 1e-6f);
#pragma unroll
        for (int i = 0; i < 4; i++) {
            int d = lane + 32 * i;
            xout[(size_t)bt * VALUE_DIM + hh * VD + d] =
                xv[i] * r * (1.f + nw[d]);
        }
    }
}

// ---------------------------------------------------------------------------
// Launch
// ---------------------------------------------------------------------------
extern "C" void kernel_launch(void* const* d_in, const int* in_sizes, int n_in,
                              void* d_out, int out_size)
{
    const float* hs    = (const float*)d_in[0];
    const float* Wqkvz = (const float*)d_in[1];
    const float* Wba   = (const float*)d_in[2];
    const float* convw = (const float*)d_in[3];
    const float* Alog  = (const float*)d_in[4];
    const float* dtb   = (const float*)d_in[5];
    const float* nw    = (const float*)d_in[6];
    const float* Wout  = (const float*)d_in[7];
    float* out = (float*)d_out;

    float *qkvz, *ba, *qn, *kn, *vv, *oo, *xx, *gg, *bb;
    cudaGetSymbolAddress((void**)&qkvz, g_qkvz);
    cudaGetSymbolAddress((void**)&ba,   g_ba);
    cudaGetSymbolAddress((void**)&qn,   g_qn);
    cudaGetSymbolAddress((void**)&kn,   g_kn);
    cudaGetSymbolAddress((void**)&vv,   g_v);
    cudaGetSymbolAddress((void**)&oo,   g_o);
    cudaGetSymbolAddress((void**)&xx,   g_x);
    cudaGetSymbolAddress((void**)&gg,   g_g);
    cudaGetSymbolAddress((void**)&bb,   g_beta);

    // 1) qkvz = hs @ W_qkvz : [4096,2048]x[2048,12288]
    tf32_gemm_kernel<<<dim3(QKVZ_N / BN, BT / BM), 256>>>(
        hs, Wqkvz, qkvz, BT, QKVZ_N, DD);

    // 2) ba = hs @ W_ba : [4096,2048]x[2048,64]
    ba_kernel<<<BT, 64>>>(hs, Wba, ba);

    // 3) conv + silu + l2norm + gating
    conv_gate_kernel<<<BT, 256>>>(qkvz, ba, convw, Alog, dtb,
                                  qn, kn, vv, gg, bb);

    // 4) gated delta rule scan
    scan_kernel<<<128, 256>>>(qn, kn, vv, gg, bb, oo);

    // 5) gated rmsnorm
    rmsnorm_kernel<<<BT, 256>>>(oo, qkvz, nw, xx);

    // 6) out = x @ W_out : [4096,4096]x[4096,2048]
    tf32_gemm_kernel<<<dim3(DD / BN, BT / BM), 256>>>(
        xx, Wout, out, BT, DD, VALUE_DIM);
}

// round 5
// speedup vs baseline: 2.7758x; 1.3878x over previous
#include <cuda_runtime.h>
#include <cuda_bf16.h>
#include <math.h>

typedef unsigned long long ull;
typedef unsigned int u32;

// Problem constants
#define BATCH 2
#define TT 2048
#define DD 2048
#define HK 16
#define HV 32
#define KD 128
#define VD 128
#define KEY_DIM 2048
#define VALUE_DIM 4096
#define QKVZ_N 12288
#define BT (BATCH*TT)

// ---------------------------------------------------------------------------
// Scratch
// ---------------------------------------------------------------------------
__device__ float g_qkvz[(size_t)BT * QKVZ_N];        // 201 MB
__device__ float g_ba  [(size_t)BT * 64];
__device__ float g_qn  [(size_t)BT * HK * KD];
__device__ float g_kn  [(size_t)BT * HK * KD];
__device__ float g_v   [(size_t)BT * HV * VD];
__device__ float g_o   [(size_t)BT * HV * VD];
__device__ float g_x   [(size_t)BT * VALUE_DIM];
__device__ float g_g   [(size_t)BT * HV];
__device__ float g_beta[(size_t)BT * HV];
__device__ float g_atf [(size_t)BT * DD];            // hs tf32-rounded
__device__ float g_w1  [(size_t)DD * QKVZ_N];        // W_qkvz tf32-rounded [K,N]
__device__ float g_w2  [(size_t)VALUE_DIM * DD];     // W_out tf32-rounded  [K,N]

// ---------------------------------------------------------------------------
// Helpers
// ---------------------------------------------------------------------------
__device__ __forceinline__ u32 f2tf(float x) {
    u32 r; asm("cvt.rna.tf32.f32 %0, %1;" : "=r"(r) : "f"(x));
    return r;
}
__device__ __forceinline__ float silu_f(float x) {
    return x / (1.f + __expf(-x));
}
__device__ __forceinline__ ull ffma2(ull a, ull b, ull c) {
    ull d; asm("fma.rn.f32x2 %0, %1, %2, %3;" : "=l"(d) : "l"(a), "l"(b), "l"(c));
    return d;
}
__device__ __forceinline__ ull fmul2(ull a, ull b) {
    ull d; asm("mul.rn.f32x2 %0, %1, %2;" : "=l"(d) : "l"(a), "l"(b));
    return d;
}
__device__ __forceinline__ ull pack2(float x, float y) {
    ull r; asm("mov.b64 %0, {%1, %2};" : "=l"(r) : "f"(x), "f"(y));
    return r;
}
__device__ __forceinline__ float lo2(ull a) { return __uint_as_float((u32)(a & 0xffffffffull)); }
__device__ __forceinline__ float hi2(ull a) { return __uint_as_float((u32)(a >> 32)); }

__device__ __forceinline__ u32 cvta_smem(const void* p) {
    u32 a;
    asm("{ .reg .u64 t; cvta.to.shared.u64 t, %1; cvt.u32.u64 %0, t; }"
        : "=r"(a) : "l"(p));
    return a;
}
__device__ __forceinline__ void cp16(u32 dst, const void* src) {
    asm volatile("cp.async.cg.shared.global [%0], [%1], 16;"
                 :: "r"(dst), "l"(src) : "memory");
}

// ---------------------------------------------------------------------------
// Pipelined tf32 mma.sync GEMM: C[M,N] = A[M,K] * B[K,N], row-major fp32
// storage, operands pre-rounded to tf32. Tile 128x128x32, 3-stage cp.async.
// A stage: 128 rows x 36 floats (32 data + 4 pad). B: 32 rows x 136 floats.
// ---------------------------------------------------------------------------
#define AROWF 36
#define BROWF 136
#define SA_FLOATS (128*AROWF)                 // 4608
#define SB_FLOATS (32*BROWF)                  // 4352
#define STAGE_FLOATS (SA_FLOATS + SB_FLOATS)  // 8960
#define STAGE_BYTES (STAGE_FLOATS*4)          // 35840
#define NSTAGES 3
#define GEMM_SMEM (NSTAGES*STAGE_BYTES)       // 107520

__device__ __forceinline__ void gemm_load_stage(
    u32 sb, const float* __restrict__ Ag, const float* __restrict__ Bg,
    int N, int K, int kiter, int buf, int tid)
{
    const u32 st = sb + (u32)buf * STAGE_BYTES;
    const int k0 = kiter * 32;
    // A: 128 rows x 8 16B-chunks = 1024 chunks
#pragma unroll
    for (int j = 0; j < 4; j++) {
        int c = tid + j * 256;
        int r = c >> 3;
        int cc = c & 7;
        cp16(st + (u32)(r * (AROWF * 4) + cc * 16),
             Ag + (size_t)r * K + k0 + cc * 4);
    }
    // B: 32 rows x 32 chunks = 1024 chunks
#pragma unroll
    for (int j = 0; j < 4; j++) {
        int c = tid + j * 256;
        int kr = c >> 5;
        int cc = c & 31;
        cp16(st + (u32)(SA_FLOATS * 4 + kr * (BROWF * 4) + cc * 16),
             Bg + (size_t)(k0 + kr) * N + cc * 4);
    }
}

__global__ __launch_bounds__(256, 2) void tf32_gemm_kernel(
    const float* __restrict__ A, const float* __restrict__ B,
    float* __restrict__ C, int M, int N, int K)
{
    extern __shared__ __align__(16) float smem[];
    const u32 sb = cvta_smem(smem);
    const int tid = threadIdx.x;
    const int bx = blockIdx.x;     // N tile
    const int by = blockIdx.y;     // M tile
    const int warp = tid >> 5;
    const int lane = tid & 31;
    const int group = lane >> 2;
    const int tg = lane & 3;
    const int warp_m = warp >> 1;
    const int warp_n = warp & 1;
    const int niters = K >> 5;

    const float* Ag = A + (size_t)(by * 128) * K;
    const float* Bg = B + (size_t)(bx * 128);

    float acc[2][8][4];
#pragma unroll
    for (int mt = 0; mt < 2; mt++)
#pragma unroll
        for (int nt = 0; nt < 8; nt++)
#pragma unroll
            for (int r = 0; r < 4; r++) acc[mt][nt][r] = 0.f;

    // prologue: stages 0,1
#pragma unroll
    for (int s = 0; s < NSTAGES - 1; s++) {
        gemm_load_stage(sb, Ag, Bg, N, K, s, s, tid);
        asm volatile("cp.async.commit_group;" ::: "memory");
    }

    int buf = 0;
    for (int i = 0; i < niters; i++) {
        asm volatile("cp.async.wait_group %0;" :: "n"(NSTAGES - 2) : "memory");
        __syncthreads();

        const float* as = smem + buf * STAGE_FLOATS;
        const float* bs = as + SA_FLOATS;

#pragma unroll
        for (int ks = 0; ks < 4; ks++) {
            const int kc = ks * 8;
            u32 af[2][4];
#pragma unroll
            for (int mt = 0; mt < 2; mt++) {
                int r0 = warp_m * 32 + mt * 16 + group;
                af[mt][0] = __float_as_uint(as[r0 * AROWF + kc + tg]);
                af[mt][1] = __float_as_uint(as[(r0 + 8) * AROWF + kc + tg]);
                af[mt][2] = __float_as_uint(as[r0 * AROWF + kc + tg + 4]);
                af[mt][3] = __float_as_uint(as[(r0 + 8) * AROWF + kc + tg + 4]);
            }
            u32 bf[8][2];
#pragma unroll
            for (int nt = 0; nt < 8; nt++) {
                int c0 = warp_n * 64 + nt * 8 + group;
                bf[nt][0] = __float_as_uint(bs[(kc + tg) * BROWF + c0]);
                bf[nt][1] = __float_as_uint(bs[(kc + tg + 4) * BROWF + c0]);
            }
#pragma unroll
            for (int mt = 0; mt < 2; mt++)
#pragma unroll
                for (int nt = 0; nt < 8; nt++) {
                    asm volatile(
                        "mma.sync.aligned.m16n8k8.row.col.f32.tf32.tf32.f32 "
                        "{%0,%1,%2,%3}, {%4,%5,%6,%7}, {%8,%9}, {%0,%1,%2,%3};\n"
                        : "+f"(acc[mt][nt][0]), "+f"(acc[mt][nt][1]),
                          "+f"(acc[mt][nt][2]), "+f"(acc[mt][nt][3])
                        : "r"(af[mt][0]), "r"(af[mt][1]), "r"(af[mt][2]), "r"(af[mt][3]),
                          "r"(bf[nt][0]), "r"(bf[nt][1]));
                }
        }

        if (i + NSTAGES - 1 < niters)
            gemm_load_stage(sb, Ag, Bg, N, K, i + NSTAGES - 1,
                            (buf + NSTAGES - 1) % NSTAGES, tid);
        asm volatile("cp.async.commit_group;" ::: "memory");
        buf = (buf + 1) % NSTAGES;
    }

    // epilogue
#pragma unroll
    for (int mt = 0; mt < 2; mt++) {
        int row = by * 128 + warp_m * 32 + mt * 16 + group;
#pragma unroll
        for (int nt = 0; nt < 8; nt++) {
            int col = bx * 128 + warp_n * 64 + nt * 8 + tg * 2;
            *(float2*)(C + (size_t)row * N + col) =
                make_float2(acc[mt][nt][0], acc[mt][nt][1]);
            *(float2*)(C + (size_t)(row + 8) * N + col) =
                make_float2(acc[mt][nt][2], acc[mt][nt][3]);
        }
    }
}

// ---------------------------------------------------------------------------
// Prep: elementwise tf32 round
// ---------------------------------------------------------------------------
__global__ __launch_bounds__(256) void convert_tf32_kernel(
    const float* __restrict__ in, float* __restrict__ out, int n4)
{
    int i = blockIdx.x * 256 + threadIdx.x;
    if (i < n4) {
        float4 v = ((const float4*)in)[i];
        v.x = __uint_as_float(f2tf(v.x));
        v.y = __uint_as_float(f2tf(v.y));
        v.z = __uint_as_float(f2tf(v.z));
        v.w = __uint_as_float(f2tf(v.w));
        ((float4*)out)[i] = v;
    }
}

// ---------------------------------------------------------------------------
// ba = hs @ W_ba
// ---------------------------------------------------------------------------
__global__ __launch_bounds__(64) void ba_kernel(
    const float* __restrict__ hs, const float* __restrict__ Wba,
    float* __restrict__ ba)
{
    __shared__ float hrow[DD];
    const int row = blockIdx.x;
    for (int i = threadIdx.x; i < DD; i += 64)
        hrow[i] = hs[(size_t)row * DD + i];
    __syncthreads();
    float acc = 0.f;
    const float* wb = Wba + threadIdx.x;
    for (int k = 0; k < DD; k++)
        acc += hrow[k] * wb[(size_t)k * 64];
    ba[(size_t)row * 64 + threadIdx.x] = acc;
}

// ---------------------------------------------------------------------------
// conv + silu + l2norm + gating
// ---------------------------------------------------------------------------
__global__ __launch_bounds__(256) void conv_gate_kernel(
    const float* __restrict__ qkvz, const float* __restrict__ ba,
    const float* __restrict__ convw, const float* __restrict__ Alog,
    const float* __restrict__ dtb,
    float* __restrict__ qn, float* __restrict__ kn, float* __restrict__ vv,
    float* __restrict__ gg, float* __restrict__ bb)
{
    const int bt = blockIdx.x;
    const int b = bt / TT;
    const int t = bt % TT;
    const int tid = threadIdx.x;
    __shared__ float buf[2 * KEY_DIM];
    __shared__ float rnorm[2 * HK];

    for (int c = tid; c < 2 * KEY_DIM; c += 256) {
        float acc = 0.f;
#pragma unroll
        for (int j = 0; j < 4; j++) {
            int ts = t - 3 + j;
            if (ts >= 0)
                acc += convw[c * 4 + j] * qkvz[((size_t)b * TT + ts) * QKVZ_N + c];
        }
        buf[c] = silu_f(acc);
    }
    __syncthreads();

    const int warp = tid >> 5;
    const int lane = tid & 31;
    for (int gi = warp; gi < 32; gi += 8) {
        float s = 0.f;
#pragma unroll
        for (int l = 0; l < 4; l++) {
            float x = buf[gi * 128 + lane + 32 * l];
            s += x * x;
        }
#pragma unroll
        for (int off = 16; off; off >>= 1)
            s += __shfl_xor_sync(0xffffffffu, s, off);
        if (lane == 0) rnorm[gi] = rsqrtf(s + 1e-6f);
    }
    __syncthreads();

    const float QSCALE = 0.08838834764831845f;
    for (int i = tid; i < KEY_DIM; i += 256) {
        int kh = i >> 7;
        int d  = i & 127;
        size_t o0 = ((size_t)bt * HK + kh) * KD + d;
        qn[o0] = buf[i] * rnorm[kh] * QSCALE;
        kn[o0] = buf[KEY_DIM + i] * rnorm[HK + kh];
    }

    for (int c = tid; c < VALUE_DIM; c += 256) {
        int cc = 2 * KEY_DIM + c;
        float acc = 0.f;
#pragma unroll
        for (int j = 0; j < 4; j++) {
            int ts = t - 3 + j;
            if (ts >= 0)
                acc += convw[cc * 4 + j] * qkvz[((size_t)b * TT + ts) * QKVZ_N + cc];
        }
        vv[(size_t)bt * VALUE_DIM + c] = silu_f(acc);
    }

    if (tid < HV) {
        float bg = ba[(size_t)bt * 64 + tid];
        float a  = ba[(size_t)bt * 64 + 32 + tid] + dtb[tid];
        bb[(size_t)bt * HV + tid] = 1.f / (1.f + __expf(-bg));
        float sp = (a > 20.f) ? a : log1pf(__expf(a));
        gg[(size_t)bt * HV + tid] = -__expf(Alog[tid]) * sp;
    }
}

// ---------------------------------------------------------------------------
// Gated delta-rule scan (unchanged from R2)
// ---------------------------------------------------------------------------
struct ScanBuf {
    ulonglong2 k[8];
    ulonglong2 q[8];
    float v, g, beta;
};

__device__ __forceinline__ void scan_load(
    ScanBuf& sb, int t, int b, int kh, int h, int kq, int vcol,
    const float* __restrict__ qn, const float* __restrict__ kn,
    const float* __restrict__ vv, const float* __restrict__ gg,
    const float* __restrict__ bb)
{
    int tc = t < TT ? t : TT - 1;
    size_t ik = (((size_t)b * TT + tc) * HK + kh) * (size_t)KD + kq * 32;
    size_t iv = (((size_t)b * TT + tc) * HV + h) * (size_t)VD + vcol;
    const ulonglong2* kp = (const ulonglong2*)(kn + ik);
    const ulonglong2* qp = (const ulonglong2*)(qn + ik);
#pragma unroll
    for (int i = 0; i < 8; i++) { sb.k[i] = kp[i]; sb.q[i] = qp[i]; }
    sb.v = vv[iv];
    size_t ig = ((size_t)b * TT + tc) * HV + h;
    sb.g = gg[ig];
    sb.beta = bb[ig];
}

__device__ __forceinline__ void scan_step(
    ull* __restrict__ S2, const ScanBuf& sb, int t, int b, int h, int kq,
    int vcol, float* __restrict__ oo)
{
    float eg = __expf(sb.g);
    ull eg2 = pack2(eg, eg);
    ull p2 = 0ull;
#pragma unroll
    for (int i = 0; i < 8; i++) {
        S2[2*i]   = fmul2(S2[2*i],   eg2);
        p2 = ffma2(sb.k[i].x, S2[2*i],   p2);
        S2[2*i+1] = fmul2(S2[2*i+1], eg2);
        p2 = ffma2(sb.k[i].y, S2[2*i+1], p2);
    }
    float p = lo2(p2) + hi2(p2);
    p += __shfl_xor_sync(0xffffffffu, p, 1);
    p += __shfl_xor_sync(0xffffffffu, p, 2);
    float delta = (sb.v - p) * sb.beta;
    ull d2 = pack2(delta, delta);
    ull o2 = 0ull;
#pragma unroll
    for (int i = 0; i < 8; i++) {
        S2[2*i]   = ffma2(sb.k[i].x, d2, S2[2*i]);
        o2 = ffma2(sb.q[i].x, S2[2*i],   o2);
        S2[2*i+1] = ffma2(sb.k[i].y, d2, S2[2*i+1]);
        o2 = ffma2(sb.q[i].y, S2[2*i+1], o2);
    }
    float o = lo2(o2) + hi2(o2);
    o += __shfl_xor_sync(0xffffffffu, o, 1);
    o += __shfl_xor_sync(0xffffffffu, o, 2);
    if (kq == 0) {
        size_t iv = (((size_t)b * TT + t) * HV + h) * (size_t)VD + vcol;
        oo[iv] = o;
    }
}

__global__ __launch_bounds__(256, 1) void scan_kernel(
    const float* __restrict__ qn, const float* __restrict__ kn,
    const float* __restrict__ vv, const float* __restrict__ gg,
    const float* __restrict__ bb, float* __restrict__ oo)
{
    const int bh2 = blockIdx.x;
    const int b = bh2 >> 6;
    const int rem = bh2 & 63;
    const int h = rem >> 1;
    const int vhalf = rem & 1;
    const int tid = threadIdx.x;
    const int colL = tid >> 2;
    const int kq = tid & 3;
    const int vcol = vhalf * 64 + colL;
    const int kh = h >> 1;

    ull S2[16];
#pragma unroll
    for (int i = 0; i < 16; i++) S2[i] = 0ull;

    ScanBuf bA, bB;
    scan_load(bA, 0, b, kh, h, kq, vcol, qn, kn, vv, gg, bb);

    for (int t = 0; t < TT; t += 2) {
        scan_load(bB, t + 1, b, kh, h, kq, vcol, qn, kn, vv, gg, bb);
        scan_step(S2, bA, t, b, h, kq, vcol, oo);
        scan_load(bA, t + 2, b, kh, h, kq, vcol, qn, kn, vv, gg, bb);
        scan_step(S2, bB, t + 1, b, h, kq, vcol, oo);
    }
}

// ---------------------------------------------------------------------------
// gated rmsnorm (stores tf32-rounded x for GEMM2's A operand)
// ---------------------------------------------------------------------------
__global__ __launch_bounds__(256) void rmsnorm_kernel(
    const float* __restrict__ oo, const float* __restrict__ qkvz,
    const float* __restrict__ nw, float* __restrict__ xout)
{
    const int bt = blockIdx.x;
    const int warp = threadIdx.x >> 5;
    const int lane = threadIdx.x & 31;

    for (int hh = warp; hh < HV; hh += 8) {
        const size_t base = ((size_t)bt * HV + hh) * (size_t)VD;
        const float* zz = qkvz + (size_t)bt * QKVZ_N + 2 * KEY_DIM + VALUE_DIM
                          + (size_t)hh * VD;
        float xv[4];
        float ss = 0.f;
#pragma unroll
        for (int i = 0; i < 4; i++) {
            int d = lane + 32 * i;
            float z = zz[d];
            float x = oo[base + d] * silu_f(z);
            xv[i] = x;
            ss += x * x;
        }
#pragma unroll
        for (int off = 16; off; off >>= 1)
            ss += __shfl_xor_sync(0xffffffffu, ss, off);
        float r = rsqrtf(ss * (1.f / 128.f) + 1e-6f);
#pragma unroll
        for (int i = 0; i < 4; i++) {
            int d = lane + 32 * i;
            xout[(size_t)bt * VALUE_DIM + hh * VD + d] =
                __uint_as_float(f2tf(xv[i] * r * (1.f + nw[d])));
        }
    }
}

// ---------------------------------------------------------------------------
// Launch
// ---------------------------------------------------------------------------
extern "C" void kernel_launch(void* const* d_in, const int* in_sizes, int n_in,
                              void* d_out, int out_size)
{
    const float* hs    = (const float*)d_in[0];
    const float* Wqkvz = (const float*)d_in[1];
    const float* Wba   = (const float*)d_in[2];
    const float* convw = (const float*)d_in[3];
    const float* Alog  = (const float*)d_in[4];
    const float* dtb   = (const float*)d_in[5];
    const float* nw    = (const float*)d_in[6];
    const float* Wout  = (const float*)d_in[7];
    float* out = (float*)d_out;

    float *qkvz, *ba, *qn, *kn, *vv, *oo, *xx, *gg, *bb, *atf, *w1, *w2;
    cudaGetSymbolAddress((void**)&qkvz, g_qkvz);
    cudaGetSymbolAddress((void**)&ba,   g_ba);
    cudaGetSymbolAddress((void**)&qn,   g_qn);
    cudaGetSymbolAddress((void**)&kn,   g_kn);
    cudaGetSymbolAddress((void**)&vv,   g_v);
    cudaGetSymbolAddress((void**)&oo,   g_o);
    cudaGetSymbolAddress((void**)&xx,   g_x);
    cudaGetSymbolAddress((void**)&gg,   g_g);
    cudaGetSymbolAddress((void**)&bb,   g_beta);
    cudaGetSymbolAddress((void**)&atf,  g_atf);
    cudaGetSymbolAddress((void**)&w1,   g_w1);
    cudaGetSymbolAddress((void**)&w2,   g_w2);

    cudaFuncSetAttribute(tf32_gemm_kernel,
                         cudaFuncAttributeMaxDynamicSharedMemorySize, GEMM_SMEM);

    // prep: elementwise tf32 rounding (A and both weight matrices stay [K,N])
    convert_tf32_kernel<<<(BT * DD / 4 + 255) / 256, 256>>>(hs, atf, BT * DD / 4);
    convert_tf32_kernel<<<(DD * QKVZ_N / 4 + 255) / 256, 256>>>(
        Wqkvz, w1, DD * QKVZ_N / 4);
    convert_tf32_kernel<<<(VALUE_DIM * DD / 4 + 255) / 256, 256>>>(
        Wout, w2, VALUE_DIM * DD / 4);

    // 1) qkvz = hs @ W_qkvz : [4096,2048]x[2048,12288]
    tf32_gemm_kernel<<<dim3(QKVZ_N / 128, BT / 128), 256, GEMM_SMEM>>>(
        atf, w1, qkvz, BT, QKVZ_N, DD);

    // 2) ba = hs @ W_ba
    ba_kernel<<<BT, 64>>>(hs, Wba, ba);

    // 3) conv + silu + l2norm + gating
    conv_gate_kernel<<<BT, 256>>>(qkvz, ba, convw, Alog, dtb, qn, kn, vv, gg, bb);

    // 4) gated delta rule scan
    scan_kernel<<<128, 256>>>(qn, kn, vv, gg, bb, oo);

    // 5) gated rmsnorm
    rmsnorm_kernel<<<BT, 256>>>(oo, qkvz, nw, xx);

    // 6) out = x @ W_out : [4096,4096]x[4096,2048]
    tf32_gemm_kernel<<<dim3(DD / 128, BT / 128), 256, GEMM_SMEM>>>(
        xx, w2, out, BT, DD, VALUE_DIM);
}